// round 1
// baseline (speedup 1.0000x reference)
#include <cuda_runtime.h>

// Problem constants
#define MTOK 20480      // B*T
#define EDIM 1024
#define TLEN 320
#define NH   16
#define HSZ  64
#define NB   64

// Scratch (device globals — allocation-free per harness rules)
__device__ float g_h   [MTOK * EDIM];      // LN output (reused for ln1 and ln2)
__device__ float g_q   [MTOK * EDIM];
__device__ float g_k   [MTOK * EDIM];
__device__ float g_v   [MTOK * EDIM];
__device__ float g_attn[MTOK * EDIM];
__device__ float g_x1  [MTOK * EDIM];
__device__ float g_u   [MTOK * 4 * EDIM];

// ---------------------------------------------------------------------------
// LayerNorm: one block per row of 1024, 256 threads x 4 elems
// ---------------------------------------------------------------------------
__global__ void ln_kernel(const float* __restrict__ x, const float* __restrict__ w,
                          const float* __restrict__ b, float* __restrict__ out) {
    int row = blockIdx.x;
    const float* xr = x + (size_t)row * EDIM;
    float* orow = out + (size_t)row * EDIM;
    float v[4];
    float s = 0.f, s2 = 0.f;
#pragma unroll
    for (int i = 0; i < 4; i++) {
        v[i] = xr[threadIdx.x + i * 256];
        s += v[i];
        s2 += v[i] * v[i];
    }
#pragma unroll
    for (int o = 16; o > 0; o >>= 1) {
        s  += __shfl_xor_sync(0xffffffffu, s, o);
        s2 += __shfl_xor_sync(0xffffffffu, s2, o);
    }
    __shared__ float ss[8], ss2[8];
    int wid = threadIdx.x >> 5;
    if ((threadIdx.x & 31) == 0) { ss[wid] = s; ss2[wid] = s2; }
    __syncthreads();
    s = 0.f; s2 = 0.f;
#pragma unroll
    for (int i = 0; i < 8; i++) { s += ss[i]; s2 += ss2[i]; }
    float mu  = s  * (1.f / EDIM);
    float var = s2 * (1.f / EDIM) - mu * mu;
    float inv = rsqrtf(var + 1e-5f);
#pragma unroll
    for (int i = 0; i < 4; i++) {
        int idx = threadIdx.x + i * 256;
        orow[idx] = (v[i] - mu) * inv * w[idx] + b[idx];
    }
}

// ---------------------------------------------------------------------------
// Generic tiled SGEMM: C[M,N] = act(A[M,K] @ W + bias) (+ residual)
//   headStride > 0: weight laid out (H, K, 64); tile base = W + (n/64)*headStride,
//                   ldw = 64 (BN=64 tiles align to heads).
//   headStride == 0: standard row-major K x N.
// BM=BN=64, BK=16, 256 threads, 4x4 microtile.
// ---------------------------------------------------------------------------
__global__ void __launch_bounds__(256)
gemm_kernel(const float* __restrict__ A, const float* __restrict__ W,
            const float* __restrict__ bias, const float* __restrict__ res,
            float* __restrict__ C, int N, int K, int headStride, int doRelu) {
    const int BM = 64, BN = 64, BK = 16;
    __shared__ float As[BK][BM + 4];   // padded: store conflicts -> 2-way
    __shared__ float Ws[BK][BN];

    int mBase = blockIdx.y * BM;
    int nBase = blockIdx.x * BN;

    const float* wBase;
    int ldw;
    if (headStride) { wBase = W + (size_t)(nBase >> 6) * headStride; ldw = 64; }
    else            { wBase = W + nBase;                              ldw = N;  }

    int tid = threadIdx.x;
    int tx = tid & 15, ty = tid >> 4;

    float acc[4][4];
#pragma unroll
    for (int i = 0; i < 4; i++)
#pragma unroll
        for (int j = 0; j < 4; j++) acc[i][j] = 0.f;

    for (int k0 = 0; k0 < K; k0 += BK) {
#pragma unroll
        for (int i = 0; i < 4; i++) {                  // A tile 64x16
            int e = tid + i * 256;
            int r = e >> 4, c = e & 15;
            As[c][r] = A[(size_t)(mBase + r) * K + k0 + c];
        }
#pragma unroll
        for (int i = 0; i < 4; i++) {                  // W tile 16x64
            int e = tid + i * 256;
            int r = e >> 6, c = e & 63;
            Ws[r][c] = wBase[(size_t)(k0 + r) * ldw + c];
        }
        __syncthreads();
#pragma unroll
        for (int k = 0; k < BK; k++) {
            float a[4], w[4];
#pragma unroll
            for (int i = 0; i < 4; i++) a[i] = As[k][ty * 4 + i];
#pragma unroll
            for (int j = 0; j < 4; j++) w[j] = Ws[k][tx * 4 + j];
#pragma unroll
            for (int i = 0; i < 4; i++)
#pragma unroll
                for (int j = 0; j < 4; j++)
                    acc[i][j] = fmaf(a[i], w[j], acc[i][j]);
        }
        __syncthreads();
    }

#pragma unroll
    for (int i = 0; i < 4; i++) {
        int m = mBase + ty * 4 + i;
#pragma unroll
        for (int j = 0; j < 4; j++) {
            int n = nBase + tx * 4 + j;
            float vv = acc[i][j];
            if (bias) vv += bias[n];
            if (doRelu) vv = fmaxf(vv, 0.f);
            if (res) vv += res[(size_t)m * N + n];
            C[(size_t)m * N + n] = vv;
        }
    }
}

// ---------------------------------------------------------------------------
// Causal attention, one block per (b, h); 320 threads = one query row each.
// K/V staged in dynamic smem (2 * 320 * 64 floats = 160 KB).
// Online softmax; q row + 64-wide output accumulator in registers.
// scale = E^-0.5 = 1/32 (reference scales by full E, not head size).
// ---------------------------------------------------------------------------
__global__ void __launch_bounds__(TLEN, 1)
attn_kernel(const float* __restrict__ q, const float* __restrict__ k,
            const float* __restrict__ v, float* __restrict__ out) {
    extern __shared__ float smem[];
    float* Ks = smem;               // [TLEN][HSZ]
    float* Vs = smem + TLEN * HSZ;  // [TLEN][HSZ]

    int b = blockIdx.x / NH;
    int h = blockIdx.x % NH;
    size_t base = (size_t)b * TLEN * EDIM + (size_t)h * HSZ;

    int tid = threadIdx.x;
    for (int idx = tid; idx < TLEN * HSZ; idx += TLEN) {
        int r = idx >> 6, d = idx & 63;
        Ks[idx] = k[base + (size_t)r * EDIM + d];
        Vs[idx] = v[base + (size_t)r * EDIM + d];
    }
    __syncthreads();

    int t = tid;  // query row
    float qr[HSZ];
#pragma unroll
    for (int d = 0; d < HSZ; d++) qr[d] = q[base + (size_t)t * EDIM + d];

    float m = -1e30f, l = 0.f;
    float acc[HSZ];
#pragma unroll
    for (int d = 0; d < HSZ; d++) acc[d] = 0.f;

    const float scale = 0.03125f;  // 1/sqrt(1024)

    for (int s = 0; s <= t; s++) {
        const float* kr = Ks + s * HSZ;
        float dot = 0.f;
#pragma unroll
        for (int d = 0; d < HSZ; d++) dot = fmaf(qr[d], kr[d], dot);
        float sc = dot * scale;
        float mn = fmaxf(m, sc);
        float corr = __expf(m - mn);
        float p = __expf(sc - mn);
        l = l * corr + p;
        m = mn;
        const float* vr = Vs + s * HSZ;
#pragma unroll
        for (int d = 0; d < HSZ; d++)
            acc[d] = fmaf(p, vr[d], acc[d] * corr);
    }

    float invl = 1.f / l;
#pragma unroll
    for (int d = 0; d < HSZ; d++)
        out[base + (size_t)t * EDIM + d] = acc[d] * invl;
}

// ---------------------------------------------------------------------------
// Launch
// ---------------------------------------------------------------------------
extern "C" void kernel_launch(void* const* d_in, const int* in_sizes, int n_in,
                              void* d_out, int out_size) {
    const float* x    = (const float*)d_in[0];
    const float* Wq   = (const float*)d_in[1];
    const float* Wk   = (const float*)d_in[2];
    const float* Wv   = (const float*)d_in[3];
    const float* Wo   = (const float*)d_in[4];
    const float* bo   = (const float*)d_in[5];
    const float* W1   = (const float*)d_in[6];
    const float* b1   = (const float*)d_in[7];
    const float* W2   = (const float*)d_in[8];
    const float* b2   = (const float*)d_in[9];
    const float* ln1w = (const float*)d_in[10];
    const float* ln1b = (const float*)d_in[11];
    const float* ln2w = (const float*)d_in[12];
    const float* ln2b = (const float*)d_in[13];
    float* out = (float*)d_out;

    void *ph, *pq, *pk, *pv, *pattn, *px1, *pu;
    cudaGetSymbolAddress(&ph, g_h);
    cudaGetSymbolAddress(&pq, g_q);
    cudaGetSymbolAddress(&pk, g_k);
    cudaGetSymbolAddress(&pv, g_v);
    cudaGetSymbolAddress(&pattn, g_attn);
    cudaGetSymbolAddress(&px1, g_x1);
    cudaGetSymbolAddress(&pu, g_u);
    float* h    = (float*)ph;
    float* q    = (float*)pq;
    float* k    = (float*)pk;
    float* v    = (float*)pv;
    float* attn = (float*)pattn;
    float* x1   = (float*)px1;
    float* u    = (float*)pu;

    const int smemAttn = 2 * TLEN * HSZ * (int)sizeof(float);  // 163840
    cudaFuncSetAttribute(attn_kernel, cudaFuncAttributeMaxDynamicSharedMemorySize, smemAttn);

    dim3 blk(256);
    dim3 gridE(EDIM / 64, MTOK / 64);        // N=1024
    dim3 gridF(4 * EDIM / 64, MTOK / 64);    // N=4096

    // 1) LN1
    ln_kernel<<<MTOK, 256>>>(x, ln1w, ln1b, h);
    // 2) Q, K, V projections (head-strided weights)
    gemm_kernel<<<gridE, blk>>>(h, Wq, nullptr, nullptr, q, EDIM, EDIM, EDIM * HSZ, 0);
    gemm_kernel<<<gridE, blk>>>(h, Wk, nullptr, nullptr, k, EDIM, EDIM, EDIM * HSZ, 0);
    gemm_kernel<<<gridE, blk>>>(h, Wv, nullptr, nullptr, v, EDIM, EDIM, EDIM * HSZ, 0);
    // 3) Causal attention
    attn_kernel<<<NB * NH, TLEN, smemAttn>>>(q, k, v, attn);
    // 4) Output projection + residual
    gemm_kernel<<<gridE, blk>>>(attn, Wo, bo, x, x1, EDIM, EDIM, 0, 0);
    // 5) LN2
    ln_kernel<<<MTOK, 256>>>(x1, ln2w, ln2b, h);
    // 6) FFN up + ReLU
    gemm_kernel<<<gridF, blk>>>(h, W1, b1, nullptr, u, 4 * EDIM, EDIM, 0, 1);
    // 7) FFN down + residual -> out
    gemm_kernel<<<gridE, blk>>>(u, W2, b2, x1, out, EDIM, 4 * EDIM, 0, 0);
}

// round 5
// speedup vs baseline: 2.8275x; 2.8275x over previous
#include <cuda_runtime.h>
#include <cstdint>
#include <cstddef>

#define MTOK 20480      // B*T
#define EDIM 1024
#define FF   4096
#define TLEN 320
#define NH   16
#define HSZ  64
#define NQKV 3072

// ---------------------------------------------------------------------------
// Helpers (baseline sm_80-level PTX only: mma.sync tf32 + cp.async)
// ---------------------------------------------------------------------------
__device__ __forceinline__ uint32_t smem_u32(const void* p) {
    uint32_t a;
    asm("{ .reg .u64 t; cvta.to.shared.u64 t, %1; cvt.u32.u64 %0, t; }" : "=r"(a) : "l"(p));
    return a;
}
__device__ __forceinline__ float to_tf32(float v) {
    uint32_t b;
    asm("cvt.rna.tf32.f32 %0, %1;" : "=r"(b) : "f"(v));
    return __uint_as_float(b);
}
__device__ __forceinline__ void mma_tf32(float c[4], const uint32_t a[4], const uint32_t b[2]) {
    asm volatile(
        "mma.sync.aligned.m16n8k8.row.col.f32.tf32.tf32.f32 "
        "{%0,%1,%2,%3}, {%4,%5,%6,%7}, {%8,%9}, {%0,%1,%2,%3};"
        : "+f"(c[0]), "+f"(c[1]), "+f"(c[2]), "+f"(c[3])
        : "r"(a[0]), "r"(a[1]), "r"(a[2]), "r"(a[3]), "r"(b[0]), "r"(b[1]));
}
#define CP_ASYNC16(dst, src) \
    asm volatile("cp.async.ca.shared.global [%0], [%1], 16;" :: "r"(dst), "l"(src))
#define CP_COMMIT()  asm volatile("cp.async.commit_group;" ::: "memory")
#define CP_WAIT(n)   asm volatile("cp.async.wait_group %0;" :: "n"(n) : "memory")

// ---------------------------------------------------------------------------
// Scratch (device globals; values stored as tf32-rounded fp32 where noted)
// ---------------------------------------------------------------------------
__device__ float g_h   [MTOK * EDIM];            // LN out (tf32)
__device__ float g_qkv [(size_t)MTOK * NQKV];    // fp32
__device__ float g_at  [MTOK * EDIM];            // attention out (tf32)
__device__ float g_x1  [MTOK * EDIM];            // fp32
__device__ float g_u   [(size_t)MTOK * FF];      // relu out (tf32)
__device__ float g_Wqkv[NQKV * EDIM];            // [N,K] tf32
__device__ float g_Wo  [EDIM * EDIM];
__device__ float g_W1  [FF * EDIM];
__device__ float g_W2  [EDIM * FF];

// ---------------------------------------------------------------------------
// LayerNorm -> tf32-rounded output
// ---------------------------------------------------------------------------
__global__ void ln_kernel(const float* __restrict__ x, const float* __restrict__ w,
                          const float* __restrict__ b, float* __restrict__ out) {
    int row = blockIdx.x;
    const float* xr = x + (size_t)row * EDIM;
    float v[4];
    float s = 0.f, s2 = 0.f;
#pragma unroll
    for (int i = 0; i < 4; i++) {
        v[i] = xr[threadIdx.x + i * 256];
        s += v[i]; s2 += v[i] * v[i];
    }
#pragma unroll
    for (int o = 16; o > 0; o >>= 1) {
        s  += __shfl_xor_sync(0xffffffffu, s, o);
        s2 += __shfl_xor_sync(0xffffffffu, s2, o);
    }
    __shared__ float ss[8], ss2[8];
    int wid = threadIdx.x >> 5;
    if ((threadIdx.x & 31) == 0) { ss[wid] = s; ss2[wid] = s2; }
    __syncthreads();
    s = 0.f; s2 = 0.f;
#pragma unroll
    for (int i = 0; i < 8; i++) { s += ss[i]; s2 += ss2[i]; }
    float mu  = s * (1.f / EDIM);
    float var = s2 * (1.f / EDIM) - mu * mu;
    float inv = rsqrtf(var + 1e-5f);
#pragma unroll
    for (int i = 0; i < 4; i++) {
        int idx = threadIdx.x + i * 256;
        out[(size_t)row * EDIM + idx] = to_tf32((v[i] - mu) * inv * w[idx] + b[idx]);
    }
}

// ---------------------------------------------------------------------------
// Weight prep: transpose to [N,K] (K contiguous) + tf32 round
// ---------------------------------------------------------------------------
__global__ void qkv_transpose_kernel(const float* __restrict__ Wq, const float* __restrict__ Wk,
                                     const float* __restrict__ Wv, float* __restrict__ o) {
    int idx = blockIdx.x * 256 + threadIdx.x;   // n*1024 + k, n in [0,3072)
    int n = idx >> 10, k = idx & 1023;
    int sel = n >> 10, r = n & 1023;
    int h = r >> 6, d = r & 63;
    const float* src = (sel == 0) ? Wq : (sel == 1) ? Wk : Wv;
    o[idx] = to_tf32(src[(h * 1024 + k) * 64 + d]);
}
__global__ void transpose_kernel(const float* __restrict__ W, float* __restrict__ o,
                                 int Kdim, int Ndim) {
    int idx = blockIdx.x * 256 + threadIdx.x;   // n*Kdim + k
    int k = idx % Kdim, n = idx / Kdim;
    o[idx] = to_tf32(W[(size_t)k * Ndim + n]);
}

// ---------------------------------------------------------------------------
// tf32 mma.sync GEMM: C[M,N] = act(A[M,K] @ B^T + bias) (+res)
//   A: [M,K] tf32-valued fp32.  B: [N,K] tf32-valued fp32 (K contiguous).
//   BM=BN=128, BK=16, 256 thr, 8 warps (2 M x 4 N), 64x32 warp tile,
//   double-buffered cp.async. Cf: fp32 out; Ct: tf32-rounded out (either null).
// ---------------------------------------------------------------------------
#define SPAD 20   // smem row stride (floats): float4-aligned, conflict-free

__device__ __forceinline__ void prefetch_tiles(const float* __restrict__ A,
                                               const float* __restrict__ B, int K,
                                               int mBase, int nBase, int kb,
                                               uint32_t sa, uint32_t sbm, int tid) {
#pragma unroll
    for (int i = 0; i < 2; i++) {
        int id = tid + i * 256;
        int row = id >> 2, c4 = id & 3;
        uint32_t so = (uint32_t)(row * SPAD + c4 * 4) * 4;
        CP_ASYNC16(sa  + so, A + (size_t)(mBase + row) * K + kb + c4 * 4);
        CP_ASYNC16(sbm + so, B + (size_t)(nBase + row) * K + kb + c4 * 4);
    }
}

__global__ void __launch_bounds__(256, 2)
gemm_tf32(const float* __restrict__ A, const float* __restrict__ B,
          const float* __restrict__ bias, const float* __restrict__ res,
          float* __restrict__ Cf, float* __restrict__ Ct,
          int N, int K, int doRelu)
{
    __shared__ float sA[2][128 * SPAD];
    __shared__ float sB[2][128 * SPAD];

    int tid = threadIdx.x;
    int wid = tid >> 5, lane = tid & 31;
    int wm = wid & 1, wn = wid >> 1;            // 2 x 4 warp grid
    int r = lane >> 2, kc = lane & 3;
    int mBase = blockIdx.y * 128, nBase = blockIdx.x * 128;

    uint32_t saA[2] = { smem_u32(&sA[0][0]), smem_u32(&sA[1][0]) };
    uint32_t saB[2] = { smem_u32(&sB[0][0]), smem_u32(&sB[1][0]) };

    float acc[4][4][4];
#pragma unroll
    for (int mt = 0; mt < 4; mt++)
#pragma unroll
        for (int nt = 0; nt < 4; nt++)
#pragma unroll
            for (int j = 0; j < 4; j++) acc[mt][nt][j] = 0.f;

    int NC = K >> 4;
    prefetch_tiles(A, B, K, mBase, nBase, 0, saA[0], saB[0], tid);
    CP_COMMIT();

    for (int c = 0; c < NC; c++) {
        if (c + 1 < NC) {
            prefetch_tiles(A, B, K, mBase, nBase, (c + 1) * 16,
                           saA[(c + 1) & 1], saB[(c + 1) & 1], tid);
            CP_COMMIT();
            CP_WAIT(1);
        } else {
            CP_WAIT(0);
        }
        __syncthreads();

        int buf = c & 1;
#pragma unroll
        for (int ks = 0; ks < 2; ks++) {
            int k0 = ks * 8;
            uint32_t afr[4][4];
#pragma unroll
            for (int mt = 0; mt < 4; mt++) {
                int base = (wm * 64 + mt * 16 + r) * SPAD + k0 + kc;
                afr[mt][0] = __float_as_uint(sA[buf][base]);
                afr[mt][1] = __float_as_uint(sA[buf][base + 8 * SPAD]);
                afr[mt][2] = __float_as_uint(sA[buf][base + 4]);
                afr[mt][3] = __float_as_uint(sA[buf][base + 8 * SPAD + 4]);
            }
            uint32_t bfr[4][2];
#pragma unroll
            for (int nt = 0; nt < 4; nt++) {
                int base = (wn * 32 + nt * 8 + r) * SPAD + k0 + kc;
                bfr[nt][0] = __float_as_uint(sB[buf][base]);
                bfr[nt][1] = __float_as_uint(sB[buf][base + 4]);
            }
#pragma unroll
            for (int mt = 0; mt < 4; mt++)
#pragma unroll
                for (int nt = 0; nt < 4; nt++)
                    mma_tf32(acc[mt][nt], afr[mt], bfr[nt]);
        }
        __syncthreads();
    }

    // Epilogue: c0/c1 at (row, 2t/2t+1), c2/c3 at (row+8, .)
#pragma unroll
    for (int nt = 0; nt < 4; nt++) {
        int gc = nBase + wn * 32 + nt * 8 + kc * 2;
        float b0 = bias ? bias[gc]     : 0.f;
        float b1 = bias ? bias[gc + 1] : 0.f;
#pragma unroll
        for (int mt = 0; mt < 4; mt++) {
            int gr = mBase + wm * 64 + mt * 16 + r;
#pragma unroll
            for (int half = 0; half < 2; half++) {
                int row = gr + half * 8;
                float v0 = acc[mt][nt][half * 2 + 0] + b0;
                float v1 = acc[mt][nt][half * 2 + 1] + b1;
                if (doRelu) { v0 = fmaxf(v0, 0.f); v1 = fmaxf(v1, 0.f); }
                if (res) {
                    float2 rr = *reinterpret_cast<const float2*>(res + (size_t)row * N + gc);
                    v0 += rr.x; v1 += rr.y;
                }
                if (Cf) {
                    float2 o = { v0, v1 };
                    *reinterpret_cast<float2*>(Cf + (size_t)row * N + gc) = o;
                }
                if (Ct) {
                    float2 o = { to_tf32(v0), to_tf32(v1) };
                    *reinterpret_cast<float2*>(Ct + (size_t)row * N + gc) = o;
                }
            }
        }
    }
}

// ---------------------------------------------------------------------------
// Causal attention: block per (b,h), 320 threads = 1 query row each.
// Reads fused qkv [M, 3072]; writes tf32-rounded output [M, 1024].
// ---------------------------------------------------------------------------
__global__ void __launch_bounds__(TLEN, 1)
attn_kernel(const float* __restrict__ qkv, float* __restrict__ outT) {
    extern __shared__ float sm[];
    float* Ks = sm;
    float* Vs = sm + TLEN * HSZ;

    int b = blockIdx.x / NH;
    int h = blockIdx.x % NH;
    size_t rowB = (size_t)b * TLEN;
    int hc = h * HSZ;

    int tid = threadIdx.x;
    for (int idx = tid; idx < TLEN * HSZ; idx += TLEN) {
        int rr = idx >> 6, d = idx & 63;
        size_t g = (rowB + rr) * NQKV + hc + d;
        Ks[idx] = qkv[g + 1024];
        Vs[idx] = qkv[g + 2048];
    }
    __syncthreads();

    int t = tid;
    float qr[HSZ];
#pragma unroll
    for (int d = 0; d < HSZ; d++) qr[d] = qkv[(rowB + t) * NQKV + hc + d];

    float m = -1e30f, l = 0.f;
    float acc[HSZ];
#pragma unroll
    for (int d = 0; d < HSZ; d++) acc[d] = 0.f;

    const float scale = 0.03125f;  // E^-0.5 (reference scales by full E)
    for (int s = 0; s <= t; s++) {
        const float* kr = Ks + s * HSZ;
        float d0 = 0.f, d1 = 0.f, d2 = 0.f, d3 = 0.f;
#pragma unroll
        for (int d = 0; d < HSZ; d += 4) {
            d0 = fmaf(qr[d],     kr[d],     d0);
            d1 = fmaf(qr[d + 1], kr[d + 1], d1);
            d2 = fmaf(qr[d + 2], kr[d + 2], d2);
            d3 = fmaf(qr[d + 3], kr[d + 3], d3);
        }
        float sc = ((d0 + d1) + (d2 + d3)) * scale;
        float mn = fmaxf(m, sc);
        float corr = __expf(m - mn);
        float p = __expf(sc - mn);
        l = l * corr + p;
        m = mn;
        const float* vr = Vs + s * HSZ;
#pragma unroll
        for (int d = 0; d < HSZ; d++) acc[d] = fmaf(p, vr[d], acc[d] * corr);
    }

    float invl = 1.f / l;
    size_t ob = (rowB + t) * EDIM + hc;
#pragma unroll
    for (int d = 0; d < HSZ; d++) outT[ob + d] = to_tf32(acc[d] * invl);
}

// ---------------------------------------------------------------------------
// Launch
// ---------------------------------------------------------------------------
extern "C" void kernel_launch(void* const* d_in, const int* in_sizes, int n_in,
                              void* d_out, int out_size) {
    const float* x    = (const float*)d_in[0];
    const float* Wq   = (const float*)d_in[1];
    const float* Wk   = (const float*)d_in[2];
    const float* Wv   = (const float*)d_in[3];
    const float* Wo   = (const float*)d_in[4];
    const float* bo   = (const float*)d_in[5];
    const float* W1   = (const float*)d_in[6];
    const float* b1   = (const float*)d_in[7];
    const float* W2   = (const float*)d_in[8];
    const float* b2   = (const float*)d_in[9];
    const float* ln1w = (const float*)d_in[10];
    const float* ln1b = (const float*)d_in[11];
    const float* ln2w = (const float*)d_in[12];
    const float* ln2b = (const float*)d_in[13];
    float* out = (float*)d_out;

    void* p;
#define SYM(var, sym) cudaGetSymbolAddress(&p, sym); float* var = (float*)p;
    SYM(h,    g_h)
    SYM(qkv,  g_qkv)
    SYM(at,   g_at)
    SYM(x1,   g_x1)
    SYM(u,    g_u)
    SYM(Wqkv, g_Wqkv)
    SYM(WoT,  g_Wo)
    SYM(W1T,  g_W1)
    SYM(W2T,  g_W2)
#undef SYM

    const int smemAttn = 2 * TLEN * HSZ * (int)sizeof(float);  // 160 KB
    cudaFuncSetAttribute(attn_kernel, cudaFuncAttributeMaxDynamicSharedMemorySize, smemAttn);

    // Weight prep (tf32-rounded, [N,K] layout)
    qkv_transpose_kernel<<<NQKV * EDIM / 256, 256>>>(Wq, Wk, Wv, Wqkv);
    transpose_kernel<<<EDIM * EDIM / 256, 256>>>(Wo, WoT, EDIM, EDIM);
    transpose_kernel<<<FF * EDIM / 256, 256>>>(W1, W1T, EDIM, FF);
    transpose_kernel<<<EDIM * FF / 256, 256>>>(W2, W2T, FF, EDIM);

    dim3 blk(256);
    // 1) LN1 -> h (tf32)
    ln_kernel<<<MTOK, 256>>>(x, ln1w, ln1b, h);
    // 2) fused QKV: [M,1024] x [3072,1024]^T -> qkv fp32
    gemm_tf32<<<dim3(NQKV / 128, MTOK / 128), blk>>>(
        h, Wqkv, nullptr, nullptr, qkv, nullptr, NQKV, EDIM, 0);
    // 3) attention -> at (tf32)
    attn_kernel<<<64 * NH, TLEN, smemAttn>>>(qkv, at);
    // 4) O-proj + bo + residual(x) -> x1 fp32
    gemm_tf32<<<dim3(EDIM / 128, MTOK / 128), blk>>>(
        at, WoT, bo, x, x1, nullptr, EDIM, EDIM, 0);
    // 5) LN2 -> h (tf32)
    ln_kernel<<<MTOK, 256>>>(x1, ln2w, ln2b, h);
    // 6) FFN up + b1 + ReLU -> u (tf32)
    gemm_tf32<<<dim3(FF / 128, MTOK / 128), blk>>>(
        h, W1T, b1, nullptr, nullptr, u, FF, EDIM, 1);
    // 7) FFN down + b2 + residual(x1) -> out fp32
    gemm_tf32<<<dim3(EDIM / 128, MTOK / 128), blk>>>(
        u, W2T, b2, x1, out, nullptr, EDIM, FF, 0);
}